// round 8
// baseline (speedup 1.0000x reference)
#include <cuda_runtime.h>
#include <cstdint>

// Problem: B=32, N=8192, DIM=256, M=1228
//   in0: x            [B, N, DIM] float32
//   in1: mask_indices [B, M]      int32
//   in2: emb_mask     [1, DIM]    float32
// out: masked_x [B*N*DIM] floats (+ mask_indices as floats if room).

#define DIM      256
#define ROWS_PB  256    // rows per block (divides N); 256 flags = 8 uint32
#define THREADS  256
#define UNROLL   4      // staging regs: 4 x float4 = 16 regs

__global__ void __launch_bounds__(THREADS, 5)   // <=51 regs -> 5 blocks/SM
fused_mask_kernel(const float* __restrict__ x,
                  const int*   __restrict__ mask_indices,
                  const float* __restrict__ emb_mask,
                  float*       __restrict__ out,
                  float*       __restrict__ out_idx,   // may be null
                  int M, int N, int blocks_per_batch)
{
    __shared__ uint32_t fl[ROWS_PB / 32];   // bitmask of masked rows (8 words)

    const int tid = threadIdx.x;
    const int b   = blockIdx.x / blocks_per_batch;
    const int blk = blockIdx.x % blocks_per_batch;
    const int r0  = blk * ROWS_PB;

    if (tid < ROWS_PB / 32) fl[tid] = 0;
    __syncthreads();

    // scan this batch's indices; set bits for rows in our range
    const int* idx_row = mask_indices + (size_t)b * M;
    for (int i = tid; i < M; i += THREADS) {
        int idx   = idx_row[i];
        int local = idx - r0;
        if ((unsigned)local < (unsigned)ROWS_PB)
            atomicOr(&fl[local >> 5], 1u << (local & 31));
        if (blk == 0 && out_idx != nullptr)
            out_idx[(size_t)b * M + i] = (float)idx;  // idx < 8192: exact in fp32
    }
    __syncthreads();

    // bitmask into registers (broadcast LDS once, conflict-free)
    uint32_t fw[ROWS_PB / 32];
    #pragma unroll
    for (int w = 0; w < ROWS_PB / 32; ++w) fw[w] = fl[w];

    const int sub  = tid >> 6;        // 0..3: row lane within a group of 4 rows
    const int col4 = tid & 63;        // float4 lane within row

    const float4 emb = reinterpret_cast<const float4*>(emb_mask)[col4];

    const size_t base = ((size_t)b * N + r0) * (DIM / 4);
    const float4* __restrict__ src = reinterpret_cast<const float4*>(x) + base;
    float4*       __restrict__ dst = reinterpret_cast<float4*>(out)     + base;

    // 64 row-iterations per thread; FULLY UNROLLED outer (static addressing),
    // UNROLL-wide load batches for MLP=4, plain (non-pipelined) to keep
    // staging at 16 regs so 5 blocks/SM fit.
    #pragma unroll
    for (int it = 0; it < ROWS_PB / 4; it += UNROLL) {
        float4 v[UNROLL];
        #pragma unroll
        for (int u = 0; u < UNROLL; ++u) {
            const int row = (it + u) * 4 + sub;
            const size_t off = (size_t)row * (DIM / 4) + col4;
            const bool masked = (fw[row >> 5] >> (row & 31)) & 1u;
            v[u] = masked ? emb : __ldcs(&src[off]);
        }
        #pragma unroll
        for (int u = 0; u < UNROLL; ++u) {
            const int row = (it + u) * 4 + sub;
            const size_t off = (size_t)row * (DIM / 4) + col4;
            __stcs(&dst[off], v[u]);
        }
    }
}

extern "C" void kernel_launch(void* const* d_in, const int* in_sizes, int n_in,
                              void* d_out, int out_size)
{
    const float* x            = (const float*)d_in[0];
    const int*   mask_indices = (const int*)d_in[1];
    const float* emb_mask     = (const float*)d_in[2];
    float*       out          = (float*)d_out;

    const int x_elems   = in_sizes[0];          // B*N*DIM
    const int idx_elems = in_sizes[1];          // B*M
    const int BN        = x_elems / DIM;        // B*N
    const int N         = 8192;
    const int B         = BN / N;
    const int M         = idx_elems / B;

    float* out_idx = (out_size >= x_elems + idx_elems)
                   ? (out + x_elems) : nullptr;

    const int blocks_per_batch = N / ROWS_PB;   // 32
    fused_mask_kernel<<<B * blocks_per_batch, THREADS>>>(
        x, mask_indices, emb_mask, out, out_idx, M, N, blocks_per_batch);
}

// round 9
// speedup vs baseline: 1.0504x; 1.0504x over previous
#include <cuda_runtime.h>
#include <cstdint>

// Problem: B=32, N=8192, DIM=256, M=1228
//   in0: x            [B, N, DIM] float32
//   in1: mask_indices [B, M]      int32
//   in2: emb_mask     [1, DIM]    float32
// out: masked_x [B*N*DIM] floats (+ mask_indices as floats if room).

#define DIM      256
#define ROWS_PB  128    // rows per block (divides N); finer blocks -> smaller tail
#define THREADS  256
#define UNROLL   4      // pipelined: ~8 float4 in flight per thread (R5 mainloop)

__global__ void __launch_bounds__(THREADS)
fused_mask_kernel(const float* __restrict__ x,
                  const int*   __restrict__ mask_indices,
                  const float* __restrict__ emb_mask,
                  float*       __restrict__ out,
                  float*       __restrict__ out_idx,   // may be null
                  int M, int N, int blocks_per_batch)
{
    __shared__ uint32_t fl[ROWS_PB / 32];   // bitmask of masked rows

    const int tid = threadIdx.x;
    const int b   = blockIdx.x / blocks_per_batch;
    const int blk = blockIdx.x % blocks_per_batch;
    const int r0  = blk * ROWS_PB;

    if (tid < ROWS_PB / 32) fl[tid] = 0;
    __syncthreads();

    // scan this batch's indices; set bits for rows in our range
    const int* idx_row = mask_indices + (size_t)b * M;
    for (int i = tid; i < M; i += THREADS) {
        int idx   = idx_row[i];
        int local = idx - r0;
        if ((unsigned)local < (unsigned)ROWS_PB)
            atomicOr(&fl[local >> 5], 1u << (local & 31));
        if (blk == 0 && out_idx != nullptr)
            out_idx[(size_t)b * M + i] = (float)idx;  // idx < 8192: exact in fp32
    }
    __syncthreads();

    // bitmask into registers (broadcast LDS once, conflict-free)
    uint32_t fw[ROWS_PB / 32];
    #pragma unroll
    for (int w = 0; w < ROWS_PB / 32; ++w) fw[w] = fl[w];

    const int sub  = tid >> 6;        // 0..3: row lane within a group of 4 rows
    const int col4 = tid & 63;        // float4 lane within row

    const float4 emb = reinterpret_cast<const float4*>(emb_mask)[col4];

    const size_t base = ((size_t)b * N + r0) * (DIM / 4);
    const float4* __restrict__ src = reinterpret_cast<const float4*>(x) + base;
    float4*       __restrict__ dst = reinterpret_cast<float4*>(out)     + base;

    // ROWS_PB/4 row-iterations per thread; software-pipelined groups of UNROLL
    constexpr int NIT    = ROWS_PB / 4;          // 32
    constexpr int GROUPS = NIT / UNROLL;         // 8

    float4 v[UNROLL];

    // prologue: load group 0
    #pragma unroll
    for (int u = 0; u < UNROLL; ++u) {
        const int row = u * 4 + sub;
        const size_t off = (size_t)row * (DIM / 4) + col4;
        const bool masked = (fw[row >> 5] >> (row & 31)) & 1u;
        v[u] = masked ? emb : __ldcs(&src[off]);
    }

    #pragma unroll
    for (int g = 0; g < GROUPS; ++g) {
        float4 nxt[UNROLL];
        if (g + 1 < GROUPS) {
            // prefetch next group while current stores drain
            #pragma unroll
            for (int u = 0; u < UNROLL; ++u) {
                const int row = ((g + 1) * UNROLL + u) * 4 + sub;
                const size_t off = (size_t)row * (DIM / 4) + col4;
                const bool masked = (fw[row >> 5] >> (row & 31)) & 1u;
                nxt[u] = masked ? emb : __ldcs(&src[off]);
            }
        }
        // store current group (streaming, evict-first)
        #pragma unroll
        for (int u = 0; u < UNROLL; ++u) {
            const int row = (g * UNROLL + u) * 4 + sub;
            const size_t off = (size_t)row * (DIM / 4) + col4;
            __stcs(&dst[off], v[u]);
        }
        #pragma unroll
        for (int u = 0; u < UNROLL; ++u) v[u] = nxt[u];
    }
}

extern "C" void kernel_launch(void* const* d_in, const int* in_sizes, int n_in,
                              void* d_out, int out_size)
{
    const float* x            = (const float*)d_in[0];
    const int*   mask_indices = (const int*)d_in[1];
    const float* emb_mask     = (const float*)d_in[2];
    float*       out          = (float*)d_out;

    const int x_elems   = in_sizes[0];          // B*N*DIM
    const int idx_elems = in_sizes[1];          // B*M
    const int BN        = x_elems / DIM;        // B*N
    const int N         = 8192;
    const int B         = BN / N;
    const int M         = idx_elems / B;

    float* out_idx = (out_size >= x_elems + idx_elems)
                   ? (out + x_elems) : nullptr;

    const int blocks_per_batch = N / ROWS_PB;   // 64
    fused_mask_kernel<<<B * blocks_per_batch, THREADS>>>(
        x, mask_indices, emb_mask, out, out_idx, M, N, blocks_per_batch);
}

// round 10
// speedup vs baseline: 1.0521x; 1.0016x over previous
#include <cuda_runtime.h>
#include <cstdint>

// Problem: B=32, N=8192, DIM=256, M=1228
//   in0: x            [B, N, DIM] float32
//   in1: mask_indices [B, M]      int32
//   in2: emb_mask     [1, DIM]    float32
// out: masked_x [B*N*DIM] floats (+ mask_indices as floats if room).

#define DIM      256
#define N_FIX    8192
#define B_MAX    32
#define ROWS_PB  64     // rows per streaming block (finer tail)
#define THREADS  256
#define UNROLL   4      // pipelined: ~8 float4 in flight per thread

#define WORDS_PER_BATCH (N_FIX / 32)          // 256 words = 1 KB per batch

// Global row bitmask: 32 batches x 8192 rows / 8 = 32 KB, L2-resident.
__device__ uint32_t g_bits[B_MAX * WORDS_PER_BATCH];

// One block per batch: build bitmask in smem, write 1 KB to global,
// and emit float-converted indices.
__global__ void __launch_bounds__(THREADS)
build_mask_kernel(const int* __restrict__ mask_indices,
                  float* __restrict__ out_idx,   // may be null
                  int M)
{
    __shared__ uint32_t sm[WORDS_PER_BATCH];
    const int tid = threadIdx.x;
    const int b   = blockIdx.x;

    // clear (256 threads x 1 word)
    sm[tid] = 0;
    __syncthreads();

    const int* idx_row = mask_indices + (size_t)b * M;
    for (int i = tid; i < M; i += THREADS) {
        int idx = idx_row[i];
        atomicOr(&sm[idx >> 5], 1u << (idx & 31));
        if (out_idx != nullptr)
            out_idx[(size_t)b * M + i] = (float)idx;  // idx < 8192: exact in fp32
    }
    __syncthreads();

    g_bits[b * WORDS_PER_BATCH + tid] = sm[tid];
}

// Streaming select-copy. No smem, no syncthreads: 2-word bitmask prelude.
__global__ void __launch_bounds__(THREADS)
stream_copy_kernel(const float* __restrict__ x,
                   const float* __restrict__ emb_mask,
                   float*       __restrict__ out,
                   int blocks_per_batch)
{
    const int tid = threadIdx.x;
    const int b   = blockIdx.x / blocks_per_batch;
    const int blk = blockIdx.x % blocks_per_batch;
    const int r0  = blk * ROWS_PB;

    // bitmask words for our ROWS_PB rows (L2-resident, broadcast)
    uint32_t fw[ROWS_PB / 32];
    #pragma unroll
    for (int w = 0; w < ROWS_PB / 32; ++w)
        fw[w] = __ldg(&g_bits[b * WORDS_PER_BATCH + (r0 >> 5) + w]);

    const int sub  = tid >> 6;        // 0..3: row lane within a group of 4 rows
    const int col4 = tid & 63;        // float4 lane within row

    const float4 emb = reinterpret_cast<const float4*>(emb_mask)[col4];

    const size_t base = ((size_t)b * N_FIX + r0) * (DIM / 4);
    const float4* __restrict__ src = reinterpret_cast<const float4*>(x) + base;
    float4*       __restrict__ dst = reinterpret_cast<float4*>(out)     + base;

    constexpr int NIT    = ROWS_PB / 4;          // 16
    constexpr int GROUPS = NIT / UNROLL;         // 4

    float4 v[UNROLL];

    // prologue: load group 0
    #pragma unroll
    for (int u = 0; u < UNROLL; ++u) {
        const int row = u * 4 + sub;
        const size_t off = (size_t)row * (DIM / 4) + col4;
        const bool masked = (fw[row >> 5] >> (row & 31)) & 1u;
        v[u] = masked ? emb : __ldcs(&src[off]);
    }

    #pragma unroll
    for (int g = 0; g < GROUPS; ++g) {
        float4 nxt[UNROLL];
        if (g + 1 < GROUPS) {
            #pragma unroll
            for (int u = 0; u < UNROLL; ++u) {
                const int row = ((g + 1) * UNROLL + u) * 4 + sub;
                const size_t off = (size_t)row * (DIM / 4) + col4;
                const bool masked = (fw[row >> 5] >> (row & 31)) & 1u;
                nxt[u] = masked ? emb : __ldcs(&src[off]);
            }
        }
        #pragma unroll
        for (int u = 0; u < UNROLL; ++u) {
            const int row = (g * UNROLL + u) * 4 + sub;
            const size_t off = (size_t)row * (DIM / 4) + col4;
            __stcs(&dst[off], v[u]);
        }
        #pragma unroll
        for (int u = 0; u < UNROLL; ++u) v[u] = nxt[u];
    }
}

extern "C" void kernel_launch(void* const* d_in, const int* in_sizes, int n_in,
                              void* d_out, int out_size)
{
    const float* x            = (const float*)d_in[0];
    const int*   mask_indices = (const int*)d_in[1];
    const float* emb_mask     = (const float*)d_in[2];
    float*       out          = (float*)d_out;

    const int x_elems   = in_sizes[0];          // B*N*DIM
    const int idx_elems = in_sizes[1];          // B*M
    const int BN        = x_elems / DIM;        // B*N
    const int B         = BN / N_FIX;
    const int M         = idx_elems / B;

    float* out_idx = (out_size >= x_elems + idx_elems)
                   ? (out + x_elems) : nullptr;

    // 1) Build per-batch bitmasks + emit float indices (one block per batch)
    build_mask_kernel<<<B, THREADS>>>(mask_indices, out_idx, M);

    // 2) Streaming select-copy
    const int blocks_per_batch = N_FIX / ROWS_PB;   // 128
    stream_copy_kernel<<<B * blocks_per_batch, THREADS>>>(
        x, emb_mask, out, blocks_per_batch);
}

// round 11
// speedup vs baseline: 1.0772x; 1.0238x over previous
#include <cuda_runtime.h>
#include <cstdint>

// Problem: B=32, N=8192, DIM=256, M=1228
//   in0: x            [B, N, DIM] float32
//   in1: mask_indices [B, M]      int32
//   in2: emb_mask     [1, DIM]    float32
// out: masked_x [B*N*DIM] floats (+ mask_indices as floats if room).

#define DIM      256
#define N_FIX    8192
#define ROWS_PB  64     // rows per block (fine tail); 64 flags = 2 uint32
#define THREADS  256
#define UNROLL   4      // pipelined: ~8 float4 in flight per thread

__global__ void __launch_bounds__(THREADS)
fused_mask_kernel(const float* __restrict__ x,
                  const int*   __restrict__ mask_indices,
                  const float* __restrict__ emb_mask,
                  float*       __restrict__ out,
                  float*       __restrict__ out_idx,   // may be null
                  int M, int blocks_per_batch)
{
    __shared__ uint32_t fl[ROWS_PB / 32];   // 2 words

    const int tid = threadIdx.x;
    const int b   = blockIdx.x / blocks_per_batch;
    const int blk = blockIdx.x % blocks_per_batch;
    const int r0  = blk * ROWS_PB;

    if (tid < ROWS_PB / 32) fl[tid] = 0;
    __syncthreads();

    // Vectorized scan of this batch's indices (int4 = 4 indices per load).
    const int* idx_row = mask_indices + (size_t)b * M;
    const int M4 = M >> 2;                       // 307 for M=1228
    const int4* idx4 = reinterpret_cast<const int4*>(idx_row);
    const bool emit = (blk == 0) && (out_idx != nullptr);

    for (int i = tid; i < M4; i += THREADS) {
        int4 q = __ldg(&idx4[i]);
        int l0 = q.x - r0, l1 = q.y - r0, l2 = q.z - r0, l3 = q.w - r0;
        if ((unsigned)l0 < (unsigned)ROWS_PB) atomicOr(&fl[l0 >> 5], 1u << (l0 & 31));
        if ((unsigned)l1 < (unsigned)ROWS_PB) atomicOr(&fl[l1 >> 5], 1u << (l1 & 31));
        if ((unsigned)l2 < (unsigned)ROWS_PB) atomicOr(&fl[l2 >> 5], 1u << (l2 & 31));
        if ((unsigned)l3 < (unsigned)ROWS_PB) atomicOr(&fl[l3 >> 5], 1u << (l3 & 31));
        if (emit) {
            float4 f = make_float4((float)q.x, (float)q.y, (float)q.z, (float)q.w);
            reinterpret_cast<float4*>(out_idx + (size_t)b * M)[i] = f;
        }
    }
    // remainder (M % 4) — none for M=1228, but stay general
    for (int i = (M4 << 2) + tid; i < M; i += THREADS) {
        int idx = idx_row[i];
        int local = idx - r0;
        if ((unsigned)local < (unsigned)ROWS_PB)
            atomicOr(&fl[local >> 5], 1u << (local & 31));
        if (emit) out_idx[(size_t)b * M + i] = (float)idx;
    }
    __syncthreads();

    // bitmask into registers
    uint32_t fw[ROWS_PB / 32];
    #pragma unroll
    for (int w = 0; w < ROWS_PB / 32; ++w) fw[w] = fl[w];

    const int sub  = tid >> 6;        // 0..3: row lane within a group of 4 rows
    const int col4 = tid & 63;        // float4 lane within row

    const float4 emb = reinterpret_cast<const float4*>(emb_mask)[col4];

    const size_t base = ((size_t)b * N_FIX + r0) * (DIM / 4);
    const float4* __restrict__ src = reinterpret_cast<const float4*>(x) + base;
    float4*       __restrict__ dst = reinterpret_cast<float4*>(out)     + base;

    constexpr int NIT    = ROWS_PB / 4;          // 16
    constexpr int GROUPS = NIT / UNROLL;         // 4

    float4 v[UNROLL];

    // prologue: load group 0
    #pragma unroll
    for (int u = 0; u < UNROLL; ++u) {
        const int row = u * 4 + sub;
        const size_t off = (size_t)row * (DIM / 4) + col4;
        const bool masked = (fw[row >> 5] >> (row & 31)) & 1u;
        v[u] = masked ? emb : __ldcs(&src[off]);
    }

    #pragma unroll
    for (int g = 0; g < GROUPS; ++g) {
        float4 nxt[UNROLL];
        if (g + 1 < GROUPS) {
            // prefetch next group while current stores drain
            #pragma unroll
            for (int u = 0; u < UNROLL; ++u) {
                const int row = ((g + 1) * UNROLL + u) * 4 + sub;
                const size_t off = (size_t)row * (DIM / 4) + col4;
                const bool masked = (fw[row >> 5] >> (row & 31)) & 1u;
                nxt[u] = masked ? emb : __ldcs(&src[off]);
            }
        }
        // store current group (streaming, evict-first)
        #pragma unroll
        for (int u = 0; u < UNROLL; ++u) {
            const int row = (g * UNROLL + u) * 4 + sub;
            const size_t off = (size_t)row * (DIM / 4) + col4;
            __stcs(&dst[off], v[u]);
        }
        #pragma unroll
        for (int u = 0; u < UNROLL; ++u) v[u] = nxt[u];
    }
}

extern "C" void kernel_launch(void* const* d_in, const int* in_sizes, int n_in,
                              void* d_out, int out_size)
{
    const float* x            = (const float*)d_in[0];
    const int*   mask_indices = (const int*)d_in[1];
    const float* emb_mask     = (const float*)d_in[2];
    float*       out          = (float*)d_out;

    const int x_elems   = in_sizes[0];          // B*N*DIM
    const int idx_elems = in_sizes[1];          // B*M
    const int BN        = x_elems / DIM;        // B*N
    const int B         = BN / N_FIX;
    const int M         = idx_elems / B;

    float* out_idx = (out_size >= x_elems + idx_elems)
                   ? (out + x_elems) : nullptr;

    const int blocks_per_batch = N_FIX / ROWS_PB;   // 128
    fused_mask_kernel<<<B * blocks_per_batch, THREADS>>>(
        x, mask_indices, emb_mask, out, out_idx, M, blocks_per_batch);
}